// round 9
// baseline (speedup 1.0000x reference)
#include <cuda_runtime.h>
#include <cuda_bf16.h>
#include <cstdint>

// Problem dims (fixed)
#define HID   1024
#define NBAT  16
#define SEQ   1024
#define MTOT  (NBAT * SEQ)        // 16384

// ============================================================================
// PTX helpers available on base sm_103 target
// ============================================================================
__device__ __forceinline__ uint32_t smem_u32_of(const void* p) {
    uint32_t a;
    asm("{ .reg .u64 t; cvta.to.shared.u64 t, %1; cvt.u32.u64 %0, t; }"
        : "=r"(a) : "l"(p));
    return a;
}

__device__ __forceinline__ void cp16(uint32_t s, const void* g) {
    asm volatile("cp.async.cg.shared.global [%0], [%1], 16;" :: "r"(s), "l"(g));
}
#define CP_COMMIT() asm volatile("cp.async.commit_group;" ::: "memory")
#define CP_WAIT(N)  asm volatile("cp.async.wait_group %0;" :: "n"(N) : "memory")

__device__ __forceinline__ void ldsm4(uint32_t* r, uint32_t addr) {
    asm volatile("ldmatrix.sync.aligned.m8n8.x4.shared.b16 {%0,%1,%2,%3}, [%4];"
        : "=r"(r[0]), "=r"(r[1]), "=r"(r[2]), "=r"(r[3]) : "r"(addr));
}

__device__ __forceinline__ void mma_bf16(float* c, const uint32_t* a, const uint32_t* b) {
    asm volatile(
        "mma.sync.aligned.m16n8k16.row.col.f32.bf16.bf16.f32 "
        "{%0,%1,%2,%3}, {%4,%5,%6,%7}, {%8,%9}, {%0,%1,%2,%3};"
        : "+f"(c[0]), "+f"(c[1]), "+f"(c[2]), "+f"(c[3])
        : "r"(a[0]), "r"(a[1]), "r"(a[2]), "r"(a[3]), "r"(b[0]), "r"(b[1]));
}

__device__ __forceinline__ uint32_t sw128(uint32_t o) { return o ^ ((o >> 3) & 0x70); }

// ============================================================================
// Device global scratch (bf16 hi/lo intermediates)
// ============================================================================
__device__ __align__(16) __nv_bfloat16 g_Xh[MTOT * HID];
__device__ __align__(16) __nv_bfloat16 g_Xl[MTOT * HID];
__device__ __align__(16) __nv_bfloat16 g_Wh[HID * HID];
__device__ __align__(16) __nv_bfloat16 g_Wl[HID * HID];
__device__ __align__(16) __nv_bfloat16 g_Qh[MTOT * HID];
__device__ __align__(16) __nv_bfloat16 g_Ql[MTOT * HID];
__device__ __align__(16) __nv_bfloat16 g_Kh[MTOT * HID];
__device__ __align__(16) __nv_bfloat16 g_Kl[MTOT * HID];
__device__ __align__(16) __nv_bfloat16 g_VTh[MTOT * HID];  // [a][b*1024+l], ld=16384
__device__ __align__(16) __nv_bfloat16 g_VTl[MTOT * HID];
__device__ __align__(16) float         g_S [MTOT * SEQ];   // scores fp32
__device__ __align__(16) __nv_bfloat16 g_Ph[MTOT * SEQ];
__device__ __align__(16) __nv_bfloat16 g_Pl[MTOT * SEQ];

// ============================================================================
// fp32 -> (bf16 hi, bf16 lo) elementwise split
// ============================================================================
__global__ void __launch_bounds__(256)
f32_to_split(const float* __restrict__ x, __nv_bfloat16* __restrict__ h,
             __nv_bfloat16* __restrict__ l, int n4)
{
    int i = blockIdx.x * blockDim.x + threadIdx.x;
    if (i >= n4) return;
    float4 v = reinterpret_cast<const float4*>(x)[i];
    __nv_bfloat16 h0 = __float2bfloat16(v.x);
    __nv_bfloat16 h1 = __float2bfloat16(v.y);
    __nv_bfloat16 h2 = __float2bfloat16(v.z);
    __nv_bfloat16 h3 = __float2bfloat16(v.w);
    __nv_bfloat16 l0 = __float2bfloat16(v.x - __bfloat162float(h0));
    __nv_bfloat16 l1 = __float2bfloat16(v.y - __bfloat162float(h1));
    __nv_bfloat16 l2 = __float2bfloat16(v.z - __bfloat162float(h2));
    __nv_bfloat16 l3 = __float2bfloat16(v.w - __bfloat162float(h3));
    reinterpret_cast<__nv_bfloat162*>(h)[2 * i + 0] = __halves2bfloat162(h0, h1);
    reinterpret_cast<__nv_bfloat162*>(h)[2 * i + 1] = __halves2bfloat162(h2, h3);
    reinterpret_cast<__nv_bfloat162*>(l)[2 * i + 0] = __halves2bfloat162(l0, l1);
    reinterpret_cast<__nv_bfloat162*>(l)[2 * i + 1] = __halves2bfloat162(l2, l3);
}

// ============================================================================
// Split-bf16 NT GEMM on mma.sync (HMMA), fragment-double-buffered:
//   D[m][n] = sum_k A[m][k]*B[n][k]  (hi*hi + hi*lo + lo*hi, fp32 accum)
//   CTA 128x128, K=1024, BK=64 (SW128 rows), 3-stage cp.async pipeline.
//   8 warps (2M x 4N), warp tile 64x32; fragments for k-step kk+1 are loaded
//   while MMAs for kk issue (removes LDSM->HMMA dependency stalls).
//   BIAS_MODE: 0 none, 1 per-col bias[n], 2 per-row bias[m]
//   OUT_SPLIT: 0 -> fp32 Cf;  1 -> bf16 pair (Ch, Cl)
// ============================================================================
#define KDEPTH   1024
#define BKC      64
#define NCHUNK   (KDEPTH / BKC)     // 16
#define TILE_B   16384              // 128 rows x 128 B
#define STAGE_B  (4 * TILE_B)       // Ah, Al, Bh, Bl
#define NSTAGE   3
#define GEMM_SMEM (1024 + NSTAGE * STAGE_B)

template<int BIAS_MODE, int OUT_SPLIT>
__global__ void __launch_bounds__(256, 1)
gemm_split(const __nv_bfloat16* __restrict__ Ah, const __nv_bfloat16* __restrict__ Al,
           int lda, size_t sA,
           const __nv_bfloat16* __restrict__ Bh, const __nv_bfloat16* __restrict__ Bl,
           int ldb, size_t sB,
           const float* __restrict__ bias,
           float* __restrict__ Cf, __nv_bfloat16* __restrict__ Ch,
           __nv_bfloat16* __restrict__ Cl,
           int ldc, size_t sC)
{
    extern __shared__ char smem[];
    const int tid  = threadIdx.x;
    const int wid  = tid >> 5;
    const int lane = tid & 31;
    const int wm   = wid >> 2;     // 0..1  (M)
    const int wn   = wid & 3;      // 0..3  (N)
    const int z    = blockIdx.z;

    Ah += (size_t)z * sA;  Al += (size_t)z * sA;
    Bh += (size_t)z * sB;  Bl += (size_t)z * sB;
    if (OUT_SPLIT) { Ch += (size_t)z * sC; Cl += (size_t)z * sC; }
    else           { Cf += (size_t)z * sC; }

    const int rowBase = blockIdx.y * 128;
    const int colBase = blockIdx.x * 128;

    const uint32_t raw  = smem_u32_of(smem);
    const uint32_t base = (raw + 1023u) & ~1023u;

    const __nv_bfloat16* aAh = Ah + (size_t)rowBase * lda;
    const __nv_bfloat16* aAl = Al + (size_t)rowBase * lda;
    const __nv_bfloat16* aBh = Bh + (size_t)colBase * ldb;
    const __nv_bfloat16* aBl = Bl + (size_t)colBase * ldb;

    // ---- async chunk loader: 4 tiles of 128 rows x 64 bf16, SW128 ----
    auto load_chunk = [&](int k0, uint32_t stg) {
#pragma unroll
        for (int it = 0; it < 4; ++it) {
            const int slot = tid + it * 256;     // 0..1023
            const int r    = slot >> 3;          // 0..127
            const int seg  = slot & 7;           // 16B segment
            const uint32_t so = sw128((uint32_t)(r * 128 + seg * 16));
            const size_t ga = (size_t)r * lda + k0 + seg * 8;
            const size_t gb = (size_t)r * ldb + k0 + seg * 8;
            cp16(stg + 0 * TILE_B + so, aAh + ga);
            cp16(stg + 1 * TILE_B + so, aAl + ga);
            cp16(stg + 2 * TILE_B + so, aBh + gb);
            cp16(stg + 3 * TILE_B + so, aBl + gb);
        }
        CP_COMMIT();
    };

    float acc[4][4][4];
#pragma unroll
    for (int mt = 0; mt < 4; ++mt)
#pragma unroll
        for (int nt = 0; nt < 4; ++nt)
#pragma unroll
            for (int e = 0; e < 4; ++e) acc[mt][nt][e] = 0.f;

    // Prologue: chunks 0 and 1
    load_chunk(0, base + 0 * STAGE_B);
    load_chunk(BKC, base + 1 * STAGE_B);

    // Per-lane intra-tile offsets (validated fragment mapping)
    const uint32_t aRow = (uint32_t)(wm * 64 + (lane & 15));                 // + mt*16
    const uint32_t aCb  = (uint32_t)((lane >> 4) << 4);                      // + kk*32
    const uint32_t bRow = (uint32_t)(wn * 32 + ((lane >> 4) << 3) + (lane & 7)); // + j*16
    const uint32_t bCb  = (uint32_t)(((lane >> 3) & 1) << 4);                // + kk*32

    // Double-buffered register fragments (buffer index resolved at unroll)
    uint32_t fah[2][4][4], fal[2][4][4], fbh[2][4][2], fbl[2][4][2];

    auto load_frags = [&](uint32_t stg, int kk, int p) {
        const uint32_t sAh = stg;
        const uint32_t sAl = stg + 1 * TILE_B;
        const uint32_t sBh = stg + 2 * TILE_B;
        const uint32_t sBl = stg + 3 * TILE_B;
#pragma unroll
        for (int j = 0; j < 2; ++j) {
            const uint32_t off = sw128((bRow + j * 16) * 128 + kk * 32 + bCb);
            uint32_t t[4];
            ldsm4(t, sBh + off);
            fbh[p][j*2][0] = t[0]; fbh[p][j*2][1] = t[1];
            fbh[p][j*2+1][0] = t[2]; fbh[p][j*2+1][1] = t[3];
            ldsm4(t, sBl + off);
            fbl[p][j*2][0] = t[0]; fbl[p][j*2][1] = t[1];
            fbl[p][j*2+1][0] = t[2]; fbl[p][j*2+1][1] = t[3];
        }
#pragma unroll
        for (int mt = 0; mt < 4; ++mt) {
            const uint32_t off = sw128((aRow + mt * 16) * 128 + kk * 32 + aCb);
            ldsm4(fah[p][mt], sAh + off);
            ldsm4(fal[p][mt], sAl + off);
        }
    };

#pragma unroll 1
    for (int i = 0; i < NCHUNK; ++i) {
        if (i + 1 < NCHUNK) { CP_WAIT(1); } else { CP_WAIT(0); }
        __syncthreads();

        // Prefetch chunk i+2 into the stage freed by chunk i-1
        if (i + 2 < NCHUNK)
            load_chunk((i + 2) * BKC, base + ((i + 2) % NSTAGE) * STAGE_B);

        const uint32_t stg = base + (i % NSTAGE) * STAGE_B;

        // First k-step fragments (only exposed LDSM latency in the chunk)
        load_frags(stg, 0, 0);

#pragma unroll
        for (int kk = 0; kk < 4; ++kk) {
            const int cur = kk & 1;
            // Prefetch next k-step's fragments while MMAs below issue
            if (kk < 3) load_frags(stg, kk + 1, cur ^ 1);
#pragma unroll
            for (int mt = 0; mt < 4; ++mt) {
#pragma unroll
                for (int nt = 0; nt < 4; ++nt) mma_bf16(acc[mt][nt], fah[cur][mt], fbh[cur][nt]);
#pragma unroll
                for (int nt = 0; nt < 4; ++nt) mma_bf16(acc[mt][nt], fah[cur][mt], fbl[cur][nt]);
#pragma unroll
                for (int nt = 0; nt < 4; ++nt) mma_bf16(acc[mt][nt], fal[cur][mt], fbh[cur][nt]);
            }
        }
    }

    // ---- Epilogue: registers -> global ----
    const int l4 = lane >> 2;
    const int l2 = (lane & 3) * 2;
#pragma unroll
    for (int mt = 0; mt < 4; ++mt) {
#pragma unroll
        for (int half = 0; half < 2; ++half) {
            const int r = rowBase + wm * 64 + mt * 16 + l4 + half * 8;
            float rbias = 0.f;
            if (BIAS_MODE == 2) rbias = __ldg(&bias[r]);
#pragma unroll
            for (int nt = 0; nt < 4; ++nt) {
                const int c = colBase + wn * 32 + nt * 8 + l2;
                float v0 = acc[mt][nt][half * 2 + 0];
                float v1 = acc[mt][nt][half * 2 + 1];
                if (BIAS_MODE == 1) {
                    float2 bv = *reinterpret_cast<const float2*>(&bias[c]);
                    v0 += bv.x; v1 += bv.y;
                } else if (BIAS_MODE == 2) {
                    v0 += rbias; v1 += rbias;
                }
                if (OUT_SPLIT == 0) {
                    float2 st; st.x = v0; st.y = v1;
                    *reinterpret_cast<float2*>(Cf + (size_t)r * ldc + c) = st;
                } else {
                    __nv_bfloat16 h0 = __float2bfloat16(v0);
                    __nv_bfloat16 h1 = __float2bfloat16(v1);
                    __nv_bfloat16 q0 = __float2bfloat16(v0 - __bfloat162float(h0));
                    __nv_bfloat16 q1 = __float2bfloat16(v1 - __bfloat162float(h1));
                    *reinterpret_cast<__nv_bfloat162*>(Ch + (size_t)r * ldc + c) =
                        __halves2bfloat162(h0, h1);
                    *reinterpret_cast<__nv_bfloat162*>(Cl + (size_t)r * ldc + c) =
                        __halves2bfloat162(q0, q1);
                }
            }
        }
    }
}

// ============================================================================
// Row softmax over 1024-wide rows; fp32 in, bf16 hi/lo split out.
// ============================================================================
__global__ void __launch_bounds__(256)
softmax_split(const float* __restrict__ S, __nv_bfloat16* __restrict__ Ph,
              __nv_bfloat16* __restrict__ Pl)
{
    const int row = blockIdx.x;
    const int t = threadIdx.x;
    const int w = t >> 5, l = t & 31;

    float4 v = *reinterpret_cast<const float4*>(S + (size_t)row * 1024 + t * 4);

    float m = fmaxf(fmaxf(v.x, v.y), fmaxf(v.z, v.w));
#pragma unroll
    for (int o = 16; o; o >>= 1) m = fmaxf(m, __shfl_xor_sync(0xffffffffu, m, o));

    __shared__ float redm[8], reds[8];
    if (l == 0) redm[w] = m;
    __syncthreads();
    float rm = fmaxf(fmaxf(fmaxf(redm[0], redm[1]), fmaxf(redm[2], redm[3])),
                     fmaxf(fmaxf(redm[4], redm[5]), fmaxf(redm[6], redm[7])));

    v.x = __expf(v.x - rm);
    v.y = __expf(v.y - rm);
    v.z = __expf(v.z - rm);
    v.w = __expf(v.w - rm);

    float s = v.x + v.y + v.z + v.w;
#pragma unroll
    for (int o = 16; o; o >>= 1) s += __shfl_xor_sync(0xffffffffu, s, o);
    if (l == 0) reds[w] = s;
    __syncthreads();
    float tot = (reds[0] + reds[1]) + (reds[2] + reds[3])
              + (reds[4] + reds[5]) + (reds[6] + reds[7]);

    const float inv = 1.0f / tot;
    float w0 = v.x * inv, w1 = v.y * inv, w2 = v.z * inv, w3 = v.w * inv;

    __nv_bfloat16 h0 = __float2bfloat16(w0), h1 = __float2bfloat16(w1);
    __nv_bfloat16 h2 = __float2bfloat16(w2), h3 = __float2bfloat16(w3);
    __nv_bfloat16 l0 = __float2bfloat16(w0 - __bfloat162float(h0));
    __nv_bfloat16 l1 = __float2bfloat16(w1 - __bfloat162float(h1));
    __nv_bfloat16 l2 = __float2bfloat16(w2 - __bfloat162float(h2));
    __nv_bfloat16 l3 = __float2bfloat16(w3 - __bfloat162float(h3));

    const size_t p2 = ((size_t)row * 1024 + t * 4) >> 1;
    reinterpret_cast<__nv_bfloat162*>(Ph)[p2 + 0] = __halves2bfloat162(h0, h1);
    reinterpret_cast<__nv_bfloat162*>(Ph)[p2 + 1] = __halves2bfloat162(h2, h3);
    reinterpret_cast<__nv_bfloat162*>(Pl)[p2 + 0] = __halves2bfloat162(l0, l1);
    reinterpret_cast<__nv_bfloat162*>(Pl)[p2 + 1] = __halves2bfloat162(l2, l3);
}

// ============================================================================
// kernel_launch
// ============================================================================
extern "C" void kernel_launch(void* const* d_in, const int* in_sizes, int n_in,
                              void* d_out, int out_size)
{
    const float* meme  = (const float*)d_in[0];
    const float* text  = (const float*)d_in[1];
    const float* emoji = (const float*)d_in[2];
    const float* Wq    = (const float*)d_in[3];
    const float* bq    = (const float*)d_in[4];
    const float* Wk    = (const float*)d_in[5];
    const float* bk    = (const float*)d_in[6];
    const float* Wv    = (const float*)d_in[7];
    const float* bv    = (const float*)d_in[8];
    float* out = (float*)d_out;

    __nv_bfloat16 *Xh, *Xl, *Wh, *Wl, *Qh, *Ql, *Kh, *Kl, *VTh, *VTl, *Ph, *Pl;
    float* S;
    cudaGetSymbolAddress((void**)&Xh, g_Xh);   cudaGetSymbolAddress((void**)&Xl, g_Xl);
    cudaGetSymbolAddress((void**)&Wh, g_Wh);   cudaGetSymbolAddress((void**)&Wl, g_Wl);
    cudaGetSymbolAddress((void**)&Qh, g_Qh);   cudaGetSymbolAddress((void**)&Ql, g_Ql);
    cudaGetSymbolAddress((void**)&Kh, g_Kh);   cudaGetSymbolAddress((void**)&Kl, g_Kl);
    cudaGetSymbolAddress((void**)&VTh, g_VTh); cudaGetSymbolAddress((void**)&VTl, g_VTl);
    cudaGetSymbolAddress((void**)&Ph, g_Ph);   cudaGetSymbolAddress((void**)&Pl, g_Pl);
    cudaGetSymbolAddress((void**)&S, g_S);

    cudaFuncSetAttribute(gemm_split<1, 1>, cudaFuncAttributeMaxDynamicSharedMemorySize, GEMM_SMEM);
    cudaFuncSetAttribute(gemm_split<2, 1>, cudaFuncAttributeMaxDynamicSharedMemorySize, GEMM_SMEM);
    cudaFuncSetAttribute(gemm_split<0, 0>, cudaFuncAttributeMaxDynamicSharedMemorySize, GEMM_SMEM);

    const size_t bstr = (size_t)SEQ * HID;          // 1M elems per batch
    const int nx4 = (MTOT * HID) / 4;
    const int nw4 = (HID * HID) / 4;

    dim3 blk(256);
    dim3 gProj(HID / 128, MTOT / 128, 1);           // (8, 128)
    dim3 gVT(MTOT / 128, HID / 128, 1);             // (128, 8)
    dim3 gAtt(SEQ / 128, SEQ / 128, NBAT);          // (8, 8, 16)

    // Q projection: Q[l][a] = meme[l][:] . Wq[a][:] + bq[a]
    f32_to_split<<<(nx4 + 255) / 256, blk>>>(meme, Xh, Xl, nx4);
    f32_to_split<<<(nw4 + 255) / 256, blk>>>(Wq, Wh, Wl, nw4);
    gemm_split<1, 1><<<gProj, blk, GEMM_SMEM>>>(Xh, Xl, HID, 0, Wh, Wl, HID, 0,
                                                bq, nullptr, Qh, Ql, HID, 0);
    // K projection
    f32_to_split<<<(nx4 + 255) / 256, blk>>>(text, Xh, Xl, nx4);
    f32_to_split<<<(nw4 + 255) / 256, blk>>>(Wk, Wh, Wl, nw4);
    gemm_split<1, 1><<<gProj, blk, GEMM_SMEM>>>(Xh, Xl, HID, 0, Wh, Wl, HID, 0,
                                                bk, nullptr, Kh, Kl, HID, 0);
    // V^T projection: VT[a][lg] = Wv[a][:] . emoji[lg][:] + bv[a]  (ldc = 16384)
    f32_to_split<<<(nx4 + 255) / 256, blk>>>(emoji, Xh, Xl, nx4);
    f32_to_split<<<(nw4 + 255) / 256, blk>>>(Wv, Wh, Wl, nw4);
    gemm_split<2, 1><<<gVT, blk, GEMM_SMEM>>>(Wh, Wl, HID, 0, Xh, Xl, HID, 0,
                                              bv, nullptr, VTh, VTl, MTOT, 0);
    // Scores: per batch  S[q][k] = Q[q][:] . K[k][:]
    gemm_split<0, 0><<<gAtt, blk, GEMM_SMEM>>>(Qh, Ql, HID, bstr, Kh, Kl, HID, bstr,
                                               nullptr, S, nullptr, nullptr, SEQ, bstr);
    // Softmax -> split weights
    softmax_split<<<MTOT, blk>>>(S, Ph, Pl);
    // Output: per batch  O[q][a] = P[q][:] . VT[a][b*1024 + :]
    gemm_split<0, 0><<<gAtt, blk, GEMM_SMEM>>>(Ph, Pl, SEQ, bstr,
                                               VTh, VTl, MTOT, (size_t)SEQ,
                                               nullptr, out, nullptr, nullptr, HID, bstr);
}